// round 12
// baseline (speedup 1.0000x reference)
#include <cuda_runtime.h>
#include <math.h>

// GRU: T=512, B=64, IC=512, HC=512, L=2
// Per layer: xproj GEMM (parallel) + one persistent kernel (512 recurrent steps,
// 128 co-resident CTAs, weights smem-resident, grid sense barrier, L2 exchange).

#define NT 512
#define NB 64
#define NH 512
#define NCTA 128

// ---- scratch (static device arrays; no allocation APIs allowed) ----
__device__ float g_Ax[(size_t)32768 * 1024];  // [T*B, 1024]
__device__ float g_Gx[(size_t)32768 * 512];   // [T*B, 512]
__device__ float g_y1[(size_t)32768 * 512];   // layer-1 output sequence
__device__ float g_h [NB * NH];
__device__ float g_rh[NB * NH];
__device__ int          g_bar_count = 0;
__device__ volatile int g_bar_sense = 0;

// ---- packed f32x2 helpers (bit-exact IEEE fp32, 2x FFMA rate) ----
__device__ __forceinline__ unsigned long long pk2(float a, float b) {
    unsigned long long r;
    asm("mov.b64 %0, {%1, %2};" : "=l"(r) : "f"(a), "f"(b));
    return r;
}
__device__ __forceinline__ void fma2(unsigned long long& d,
                                     unsigned long long a, unsigned long long b) {
    asm("fma.rn.f32x2 %0, %1, %2, %3;" : "=l"(d) : "l"(a), "l"(b), "l"(d));
}
__device__ __forceinline__ float2 up2(unsigned long long v) {
    float lo, hi;
    asm("mov.b64 {%0, %1}, %2;" : "=f"(lo), "=f"(hi) : "l"(v));
    return make_float2(lo, hi);
}
__device__ __forceinline__ float sigf(float x) { return 1.0f / (1.0f + expf(-x)); }

// ---- grid-wide sense-reversing barrier (all 128 CTAs co-resident) ----
__device__ __forceinline__ void grid_barrier(int target) {
    __syncthreads();
    if (threadIdx.x == 0) {
        __threadfence();
        if (atomicAdd(&g_bar_count, 1) == NCTA - 1) {
            atomicExch(&g_bar_count, 0);
            __threadfence();
            g_bar_sense = target;
        } else {
            while (g_bar_sense != target) { __nanosleep(20); }
        }
        __threadfence();
    }
    __syncthreads();
}

// ---- input projection GEMM: C[32768 x 1536] = X[32768 x 512] @ Wc^T + bias ----
__global__ void xproj_kernel(const float* __restrict__ Xext,
                             const float* __restrict__ W1,
                             const float* __restrict__ W2,
                             const float* __restrict__ b1,
                             const float* __restrict__ b2,
                             int layer, int use_y1) {
    const float* __restrict__ X = use_y1 ? g_y1 : Xext;
    __shared__ float Xs[16][132];
    __shared__ float Ws[16][132];
    int tid = threadIdx.x;
    int tx = tid & 15, ty = tid >> 4;
    int row0 = blockIdx.y * 128;
    int col0 = blockIdx.x * 128;
    const float* W1l = W1 + (size_t)layer * 1024 * 1024;
    const float* W2l = W2 + (size_t)layer * 512 * 1024;

    unsigned long long acc[8][4];
#pragma unroll
    for (int i = 0; i < 8; i++)
#pragma unroll
        for (int j = 0; j < 4; j++) acc[i][j] = 0ull;

    for (int k0 = 0; k0 < 512; k0 += 16) {
#pragma unroll
        for (int u = 0; u < 2; u++) {
            int f = tid + u * 256;
            int r = f >> 2;
            int kq = (f & 3) * 4;
            float4 v = *(const float4*)&X[(size_t)(row0 + r) * 512 + k0 + kq];
            Xs[kq + 0][r] = v.x; Xs[kq + 1][r] = v.y;
            Xs[kq + 2][r] = v.z; Xs[kq + 3][r] = v.w;
        }
#pragma unroll
        for (int u = 0; u < 2; u++) {
            int f = tid + u * 256;
            int j = f >> 2;
            int kq = (f & 3) * 4;
            int jg = col0 + j;
            const float* wp = (jg < 1024) ? (W1l + (size_t)jg * 1024)
                                          : (W2l + (size_t)(jg - 1024) * 1024);
            float4 v = *(const float4*)&wp[k0 + kq];
            Ws[kq + 0][j] = v.x; Ws[kq + 1][j] = v.y;
            Ws[kq + 2][j] = v.z; Ws[kq + 3][j] = v.w;
        }
        __syncthreads();
#pragma unroll
        for (int k = 0; k < 16; k++) {
            float a8[8];
            *(float4*)&a8[0] = *(const float4*)&Xs[k][ty * 8];
            *(float4*)&a8[4] = *(const float4*)&Xs[k][ty * 8 + 4];
            ulonglong2 bA = *(const ulonglong2*)&Ws[k][tx * 8];
            ulonglong2 bB = *(const ulonglong2*)&Ws[k][tx * 8 + 4];
#pragma unroll
            for (int i = 0; i < 8; i++) {
                unsigned long long ai = pk2(a8[i], a8[i]);
                fma2(acc[i][0], ai, bA.x);
                fma2(acc[i][1], ai, bA.y);
                fma2(acc[i][2], ai, bB.x);
                fma2(acc[i][3], ai, bB.y);
            }
        }
        __syncthreads();
    }
#pragma unroll
    for (int i = 0; i < 8; i++) {
        int r = row0 + ty * 8 + i;
#pragma unroll
        for (int jq = 0; jq < 4; jq++) {
            float2 v = up2(acc[i][jq]);
            int c = col0 + tx * 8 + jq * 2;
            if (c < 1024) {
                g_Ax[(size_t)r * 1024 + c]     = v.x + b1[layer * 1024 + c];
                g_Ax[(size_t)r * 1024 + c + 1] = v.y + b1[layer * 1024 + c + 1];
            } else {
                int cc = c - 1024;
                g_Gx[(size_t)r * 512 + cc]     = v.x + b2[layer * 512 + cc];
                g_Gx[(size_t)r * 512 + cc + 1] = v.y + b2[layer * 512 + cc + 1];
            }
        }
    }
}

// ---- persistent recurrent kernel ----
// 128 CTAs = 16 col-groups (cg) x 8 batch-groups (bg); 256 threads/CTA.
// Phase1 cols per CTA: r-cols [cg*32, cg*32+32) and z-cols [512+cg*32, +32)
//   -> z stays CTA-local (smem zs), no global z traffic.
// Phase2 cols per CTA: [cg*32, +32), k split in two halves + smem reduction.
// smem floats: w1s 32768 | w2s 16384 | hd 8192 (h then rh, dup-packed) |
//              red 256 | zs 256  = 57856 floats = 231424 B
#define OFF_W2S 32768
#define OFF_HD  49152
#define OFF_RED 57344
#define OFF_ZS  57600
#define PERSIST_SMEM (57856 * 4)

__global__ __launch_bounds__(256, 1)
void persist_kernel(const float* __restrict__ hiddens,
                    const float* __restrict__ W1,
                    const float* __restrict__ W2,
                    float* __restrict__ Yext,
                    float* __restrict__ hs_out,
                    int layer, int useY1) {
    extern __shared__ float sm[];
    float4* w1s = (float4*)sm;                    // [256 kk][32 jp]
    float4* w2s = (float4*)(sm + OFF_W2S);        // [256 kk][16 jp]
    float4* hd  = (float4*)(sm + OFF_HD);         // [256 kk][8 b] dup-packed
    float2* red = (float2*)(sm + OFF_RED);        // [16 jp][8 b]
    float2* zs  = (float2*)(sm + OFF_ZS);         // [16 jp][8 b]
    const ulonglong2* w1u = (const ulonglong2*)w1s;
    const ulonglong2* w2u = (const ulonglong2*)w2s;
    const ulonglong2* hdu = (const ulonglong2*)hd;

    int tid = threadIdx.x;
    int cg = blockIdx.x & 15, bg = blockIdx.x >> 4;
    int b0 = bg * 8;
    float* Y = useY1 ? g_y1 : Yext;
    const float* W1h = W1 + (size_t)layer * 1024 * 1024 + 512;
    const float* W2h = W2 + (size_t)layer * 512 * 1024 + 512;

    // ---- stage recurrent weights ONCE ----
    // w1s[kk][jp]: jp<16 -> r-row j=cg*32+2*jp ; jp>=16 -> z-row j=512+cg*32+2*(jp-16)
    // float4 = (w[j,k0], w[j+1,k0], w[j,k1], w[j+1,k1]) with k0=2kk, k1=2kk+1
    for (int idx = tid; idx < 8192; idx += 256) {
        int jp = idx & 31, kk = idx >> 5;
        int jr = (jp < 16) ? (cg * 32 + 2 * jp) : (512 + cg * 32 + 2 * (jp - 16));
        const float* r = W1h + (size_t)jr * 1024 + 2 * kk;
        float2 a = *(const float2*)r;
        float2 c = *(const float2*)(r + 1024);
        w1s[kk * 32 + jp] = make_float4(a.x, c.x, a.y, c.y);
    }
    for (int idx = tid; idx < 4096; idx += 256) {
        int jp = idx & 15, kk = idx >> 4;
        int jr = cg * 32 + 2 * jp;
        const float* r = W2h + (size_t)jr * 1024 + 2 * kk;
        float2 a = *(const float2*)r;
        float2 c = *(const float2*)(r + 1024);
        w2s[kk * 16 + jp] = make_float4(a.x, c.x, a.y, c.y);
    }

    // thread roles
    int jp1 = tid >> 3;        // 0..31 (phase1 col-pair)
    int b   = tid & 7;         // local batch
    int bglob = b0 + b;
    int kh  = tid >> 7;        // phase2 k-half
    int jp2 = (tid & 127) >> 3;// 0..15 (phase2 col-pair)
    int sense = 0;
    float oldh0 = 0.f, oldh1 = 0.f;

    for (int t = 0; t < NT; t++) {
        // ---- stage h (dup-packed): hd[kk][b] = (h[b,k0],h[b,k0],h[b,k1],h[b,k1]) ----
        if (t == 0) {
            for (int i = tid; i < 2048; i += 256) {
                int bb = i & 7, kk = i >> 3;
                float2 v = *(const float2*)&hiddens[layer * 512 + 2 * kk];
                hd[kk * 8 + bb] = make_float4(v.x, v.x, v.y, v.y);
            }
        } else {
            for (int i = tid; i < 2048; i += 256) {
                int bb = i & 7, kk = i >> 3;
                float2 v = __ldcg((const float2*)&g_h[(b0 + bb) * 512 + 2 * kk]);
                hd[kk * 8 + bb] = make_float4(v.x, v.x, v.y, v.y);
            }
        }
        __syncthreads();

        // ---- phase1: pre = Ax[t] + h @ W1h^T ; r -> rh (global), z -> zs (local) ----
        {
            unsigned long long c0 = 0ull, c1 = 0ull;
#pragma unroll 8
            for (int kk = 0; kk < 256; kk++) {
                ulonglong2 wv = w1u[kk * 32 + jp1];
                ulonglong2 hv = hdu[kk * 8 + b];
                fma2(c0, wv.x, hv.x);
                fma2(c1, wv.y, hv.y);
            }
            float2 u0 = up2(c0), u1 = up2(c1);
            float pre0 = u0.x + u1.x, pre1 = u0.y + u1.y;
            if (jp1 < 16) {
                int j0 = cg * 32 + 2 * jp1;
                float2 ax = *(const float2*)&g_Ax[((size_t)t * 64 + bglob) * 1024 + j0];
                float r0 = sigf(pre0 + ax.x), r1 = sigf(pre1 + ax.y);
                float4 hh = hd[(cg * 16 + jp1) * 8 + b];
                oldh0 = hh.x; oldh1 = hh.z;
                __stcg((float2*)&g_rh[bglob * 512 + j0],
                       make_float2(r0 * hh.x, r1 * hh.z));
            } else {
                int j0 = 512 + cg * 32 + 2 * (jp1 - 16);
                float2 ax = *(const float2*)&g_Ax[((size_t)t * 64 + bglob) * 1024 + j0];
                zs[(jp1 - 16) * 8 + b] = make_float2(sigf(pre0 + ax.x), sigf(pre1 + ax.y));
            }
        }
        sense ^= 1; grid_barrier(sense);

        // ---- stage rh into hd (overwrites h; old h kept in regs) ----
        for (int i = tid; i < 2048; i += 256) {
            int bb = i & 7, kk = i >> 3;
            float2 v = __ldcg((const float2*)&g_rh[(b0 + bb) * 512 + 2 * kk]);
            hd[kk * 8 + bb] = make_float4(v.x, v.x, v.y, v.y);
        }
        __syncthreads();

        // ---- phase2: g = tanh(Gx + rh @ W2h^T); h = z*h + (1-z)*g ----
        {
            unsigned long long d0 = 0ull, d1 = 0ull;
            int kb = kh << 7;
#pragma unroll 8
            for (int q = 0; q < 128; q++) {
                int kk = kb + q;
                ulonglong2 wv = w2u[kk * 16 + jp2];
                ulonglong2 hv = hdu[kk * 8 + b];
                fma2(d0, wv.x, hv.x);
                fma2(d1, wv.y, hv.y);
            }
            float2 e0 = up2(d0), e1 = up2(d1);
            float s0 = e0.x + e1.x, s1 = e0.y + e1.y;
            if (kh == 1) red[jp2 * 8 + b] = make_float2(s0, s1);
            __syncthreads();
            if (kh == 0) {
                float2 rv = red[jp2 * 8 + b];
                float tot0 = s0 + rv.x, tot1 = s1 + rv.y;
                int j0 = cg * 32 + 2 * jp2;
                size_t row = ((size_t)t * 64 + bglob) * 512 + j0;
                float2 gx = *(const float2*)&g_Gx[row];
                float g0 = tanhf(tot0 + gx.x), g1 = tanhf(tot1 + gx.y);
                float2 zz = zs[jp2 * 8 + b];
                float h0 = zz.x * oldh0 + (1.0f - zz.x) * g0;
                float h1 = zz.y * oldh1 + (1.0f - zz.y) * g1;
                __stcg((float2*)&g_h[bglob * 512 + j0], make_float2(h0, h1));
                *(float2*)&Y[row] = make_float2(h0, h1);
                if (t == NT - 1)
                    *(float2*)&hs_out[bglob * 512 + j0] = make_float2(h0, h1);
            }
        }
        sense ^= 1; grid_barrier(sense);
    }
}

extern "C" void kernel_launch(void* const* d_in, const int* in_sizes, int n_in,
                              void* d_out, int out_size) {
    const float* x       = (const float*)d_in[0];  // [512,64,512]
    const float* hiddens = (const float*)d_in[1];  // [2,1,512]
    const float* W1      = (const float*)d_in[2];  // [2,1024,1024]
    const float* b1      = (const float*)d_in[3];  // [2,1024]
    const float* W2      = (const float*)d_in[4];  // [2,512,1024]
    const float* b2      = (const float*)d_in[5];  // [2,512]
    float* out = (float*)d_out;                    // out [T,B,512] then hs [2,B,512]
    float* hs_out = out + (size_t)NT * NB * NH;

    static int attr_done = 0;
    if (!attr_done) {
        cudaFuncSetAttribute(persist_kernel,
                             cudaFuncAttributeMaxDynamicSharedMemorySize, PERSIST_SMEM);
        attr_done = 1;
    }

    for (int layer = 0; layer < 2; layer++) {
        xproj_kernel<<<dim3(12, 256), 256>>>(x, W1, W2, b1, b2, layer, layer == 1);
        persist_kernel<<<NCTA, 256, PERSIST_SMEM>>>(
            hiddens, W1, W2, out, hs_out + (size_t)layer * NB * NH,
            layer, layer == 0);
    }
}

// round 14
// speedup vs baseline: 1.1538x; 1.1538x over previous
#include <cuda_runtime.h>
#include <math.h>

// GRU: T=512, B=64, IC=512, HC=512, L=2
// Per layer: xproj GEMM + persistent kernel (512 steps, 128 co-resident CTAs).
// Step structure (k-split phase2 -> rh never leaves the CTA):
//   stage h -> phaseA (r,z for local 32-col slice; K=512) -> phaseB (partial
//   rh@W2h over local 32 k's for ALL 512 j) -> barrier -> reduce 16 partials +
//   tanh + h update -> barrier.

#define NT 512
#define NB 64
#define NH 512
#define NCTA 128

// ---- scratch (static device arrays; no allocation APIs allowed) ----
__device__ float g_Ax[(size_t)32768 * 1024];  // [T*B, 1024]
__device__ float g_Gx[(size_t)32768 * 512];   // [T*B, 512]
__device__ float g_y1[(size_t)32768 * 512];   // layer-1 output sequence
__device__ float g_h [NB * NH];
__device__ float g_part[8 * 16 * 8 * 512];    // [bg][cg][b][j] phase2 partials
__device__ int          g_bar_count = 0;
__device__ volatile int g_bar_sense = 0;

// ---- packed f32x2 helpers (bit-exact IEEE fp32, 2x FFMA rate) ----
__device__ __forceinline__ unsigned long long pk2(float a, float b) {
    unsigned long long r;
    asm("mov.b64 %0, {%1, %2};" : "=l"(r) : "f"(a), "f"(b));
    return r;
}
__device__ __forceinline__ void fma2(unsigned long long& d,
                                     unsigned long long a, unsigned long long b) {
    asm("fma.rn.f32x2 %0, %1, %2, %3;" : "=l"(d) : "l"(a), "l"(b), "l"(d));
}
__device__ __forceinline__ float2 up2(unsigned long long v) {
    float lo, hi;
    asm("mov.b64 {%0, %1}, %2;" : "=f"(lo), "=f"(hi) : "l"(v));
    return make_float2(lo, hi);
}
__device__ __forceinline__ float sigf(float x) { return 1.0f / (1.0f + expf(-x)); }
// bank swizzle values {0,1,4,5}: cosets of {0,2,4,6} stay distinct under XOR
__device__ __forceinline__ int XS(int r) { return (r & 1) | ((r & 2) << 1); }

// ---- grid-wide sense-reversing barrier; all threads fence before arriving ----
__device__ __forceinline__ void grid_barrier(int target) {
    __threadfence();
    __syncthreads();
    if (threadIdx.x == 0) {
        if (atomicAdd(&g_bar_count, 1) == NCTA - 1) {
            atomicExch(&g_bar_count, 0);
            __threadfence();
            g_bar_sense = target;
        } else {
            while (g_bar_sense != target) {}
        }
        __threadfence();
    }
    __syncthreads();
}

// ---- input projection GEMM: C[32768 x 1536] = X[32768 x 512] @ Wc^T + bias ----
__global__ void xproj_kernel(const float* __restrict__ Xext,
                             const float* __restrict__ W1,
                             const float* __restrict__ W2,
                             const float* __restrict__ b1,
                             const float* __restrict__ b2,
                             int layer, int use_y1) {
    const float* __restrict__ X = use_y1 ? g_y1 : Xext;
    __shared__ float Xs[16][132];
    __shared__ float Ws[16][132];
    int tid = threadIdx.x;
    int tx = tid & 15, ty = tid >> 4;
    int row0 = blockIdx.y * 128;
    int col0 = blockIdx.x * 128;
    const float* W1l = W1 + (size_t)layer * 1024 * 1024;
    const float* W2l = W2 + (size_t)layer * 512 * 1024;

    unsigned long long acc[8][4];
#pragma unroll
    for (int i = 0; i < 8; i++)
#pragma unroll
        for (int j = 0; j < 4; j++) acc[i][j] = 0ull;

    for (int k0 = 0; k0 < 512; k0 += 16) {
#pragma unroll
        for (int u = 0; u < 2; u++) {
            int f = tid + u * 256;
            int r = f >> 2;
            int kq = (f & 3) * 4;
            float4 v = *(const float4*)&X[(size_t)(row0 + r) * 512 + k0 + kq];
            Xs[kq + 0][r] = v.x; Xs[kq + 1][r] = v.y;
            Xs[kq + 2][r] = v.z; Xs[kq + 3][r] = v.w;
        }
#pragma unroll
        for (int u = 0; u < 2; u++) {
            int f = tid + u * 256;
            int j = f >> 2;
            int kq = (f & 3) * 4;
            int jg = col0 + j;
            const float* wp = (jg < 1024) ? (W1l + (size_t)jg * 1024)
                                          : (W2l + (size_t)(jg - 1024) * 1024);
            float4 v = *(const float4*)&wp[k0 + kq];
            Ws[kq + 0][j] = v.x; Ws[kq + 1][j] = v.y;
            Ws[kq + 2][j] = v.z; Ws[kq + 3][j] = v.w;
        }
        __syncthreads();
#pragma unroll
        for (int k = 0; k < 16; k++) {
            float a8[8];
            *(float4*)&a8[0] = *(const float4*)&Xs[k][ty * 8];
            *(float4*)&a8[4] = *(const float4*)&Xs[k][ty * 8 + 4];
            ulonglong2 bA = *(const ulonglong2*)&Ws[k][tx * 8];
            ulonglong2 bB = *(const ulonglong2*)&Ws[k][tx * 8 + 4];
#pragma unroll
            for (int i = 0; i < 8; i++) {
                unsigned long long ai = pk2(a8[i], a8[i]);
                fma2(acc[i][0], ai, bA.x);
                fma2(acc[i][1], ai, bA.y);
                fma2(acc[i][2], ai, bB.x);
                fma2(acc[i][3], ai, bB.y);
            }
        }
        __syncthreads();
    }
#pragma unroll
    for (int i = 0; i < 8; i++) {
        int r = row0 + ty * 8 + i;
#pragma unroll
        for (int jq = 0; jq < 4; jq++) {
            float2 v = up2(acc[i][jq]);
            int c = col0 + tx * 8 + jq * 2;
            if (c < 1024) {
                g_Ax[(size_t)r * 1024 + c]     = v.x + b1[layer * 1024 + c];
                g_Ax[(size_t)r * 1024 + c + 1] = v.y + b1[layer * 1024 + c + 1];
            } else {
                int cc = c - 1024;
                g_Gx[(size_t)r * 512 + cc]     = v.x + b2[layer * 512 + cc];
                g_Gx[(size_t)r * 512 + cc + 1] = v.y + b2[layer * 512 + cc + 1];
            }
        }
    }
}

// ---- persistent recurrent kernel ----
// smem floats (contiguous): w1 32768 | w2 16384 | hd 8192 | rhd 512 | zs 256
//   = 58112 floats = 232448 bytes
#define OFF_W2  32768
#define OFF_HD  49152
#define OFF_RHD 57344
#define OFF_ZS  57856
#define PERSIST_SMEM (58112 * 4)

__global__ __launch_bounds__(256, 1)
void persist_kernel(const float* __restrict__ hiddens,
                    const float* __restrict__ W1,
                    const float* __restrict__ W2,
                    float* __restrict__ Yext,
                    float* __restrict__ hs_out,
                    int layer, int useY1) {
    extern __shared__ float sm[];
    float4*     w1f = (float4*)sm;                 // [256 kk][32 jp] swizzled
    ulonglong2* w1u = (ulonglong2*)sm;
    float4*     w2f = (float4*)(sm + OFF_W2);      // [32 k][128 m] i-major layout
    ulonglong2* w2u = (ulonglong2*)(sm + OFF_W2);
    float4*     hdf = (float4*)(sm + OFF_HD);      // [256 kk][8 b] dup, swizzled
    ulonglong2* hdu = (ulonglong2*)(sm + OFF_HD);
    float*      hdF = sm + OFF_HD;
    float2*     rhd = (float2*)(sm + OFF_RHD);     // [32 k][8 b] dup
    unsigned long long* rhu = (unsigned long long*)(sm + OFF_RHD);
    float*      zs  = sm + OFF_ZS;                 // [32 zl][8 b]

    int tid = threadIdx.x;
    int cg = blockIdx.x & 15, bg = blockIdx.x >> 4;
    int b0 = bg * 8;
    float* Y = useY1 ? g_y1 : Yext;
    const float* W1h = W1 + (size_t)layer * 1024 * 1024 + 512;
    const float* W2h = W2 + (size_t)layer * 512 * 1024 + 512;

    // ---- stage W1h slice once: [256 kk][32 jp] ----
    // jp<16: r rows (j = cg*32 + 2jp,+1); jp>=16: z rows (j = 512+cg*32+2(jp-16),+1)
    // float4 = (w[j,k0], w[j+1,k0], w[j,k1], w[j+1,k1]), k0=2kk, k1=2kk+1
    for (int idx = tid; idx < 8192; idx += 256) {
        int jp = idx & 31, kk = idx >> 5;
        int jr = (jp < 16) ? (cg * 32 + 2 * jp) : (512 + cg * 32 + 2 * (jp - 16));
        const float* r = W1h + (size_t)jr * 1024 + 2 * kk;
        float2 a = *(const float2*)r;
        float2 c = *(const float2*)(r + 1024);
        w1f[kk * 32 + ((jp & 24) | ((jp & 7) ^ XS(kk >> 6)))] =
            make_float4(a.x, c.x, a.y, c.y);
    }
    // ---- stage W2h k-slice once: F(k,m) = rows (4m..4m+3) at col cg*32+k ----
    // storage index: k*128 + (m&3)*32 + (m>>2)  (i-major for 1-wavefront loads)
    for (int idx = tid; idx < 4096; idx += 256) {
        int m = idx & 127, k = idx >> 7;
        const float* bp_ = W2h + cg * 32 + k;
        w2f[k * 128 + (m & 3) * 32 + (m >> 2)] =
            make_float4(bp_[(size_t)(4 * m + 0) * 1024], bp_[(size_t)(4 * m + 1) * 1024],
                        bp_[(size_t)(4 * m + 2) * 1024], bp_[(size_t)(4 * m + 3) * 1024]);
    }

    // thread roles
    int kh = tid & 3, bp = (tid >> 2) & 3, jq = tid >> 4;     // phaseA
    int xs = XS(kh);
    int jpx0 = (jq * 2) ^ xs, jpx1 = (jq * 2 + 1) ^ xs;
    int bx0 = (bp * 2) ^ xs, bx1 = (bp * 2 + 1) ^ xs;
    int jg = tid >> 3, bB = tid & 7;                          // phaseB
    int ju = tid & 31, bu = tid >> 5;                         // update
    int sense = 0;

    for (int t = 0; t < NT; t++) {
        // ---- stage h dup-packed: hd[kk][b^xs] = (h[b,2kk] x2, h[b,2kk+1] x2) ----
        if (t == 0) {
            for (int i = tid; i < 2048; i += 256) {
                int bb = i & 7, kk = i >> 3;
                float2 v = *(const float2*)&hiddens[layer * 512 + 2 * kk];
                hdf[kk * 8 + (bb ^ XS(kk >> 6))] = make_float4(v.x, v.x, v.y, v.y);
            }
        } else {
            for (int i = tid; i < 2048; i += 256) {
                int bb = i & 7, kk = i >> 3;
                float2 v = __ldcg((const float2*)&g_h[(b0 + bb) * 512 + 2 * kk]);
                hdf[kk * 8 + (bb ^ XS(kk >> 6))] = make_float4(v.x, v.x, v.y, v.y);
            }
        }
        __syncthreads();

        // ---- phaseA: pre = h @ W1h^T over K=512 (ksplit-4), 4 cols x 2 b ----
        unsigned long long a00 = 0, a01 = 0, a10 = 0, a11 = 0;
        {
            int kkb = kh * 64;
#pragma unroll 8
            for (int q = 0; q < 64; q++) {
                int kk = kkb + q;
                ulonglong2 w0 = w1u[kk * 32 + jpx0];
                ulonglong2 w1 = w1u[kk * 32 + jpx1];
                ulonglong2 h0 = hdu[kk * 8 + bx0];
                ulonglong2 h1 = hdu[kk * 8 + bx1];
                fma2(a00, w0.x, h0.x); fma2(a00, w0.y, h0.y);
                fma2(a01, w0.x, h1.x); fma2(a01, w0.y, h1.y);
                fma2(a10, w1.x, h0.x); fma2(a10, w1.y, h0.y);
                fma2(a11, w1.x, h1.x); fma2(a11, w1.y, h1.y);
            }
        }
        // butterfly reduce over kh lanes (lane bits 0..1); exact (commutative adds)
        float2 v00 = up2(a00), v01 = up2(a01), v10 = up2(a10), v11 = up2(a11);
#pragma unroll
        for (int m = 1; m <= 2; m <<= 1) {
            v00.x += __shfl_xor_sync(0xffffffffu, v00.x, m);
            v00.y += __shfl_xor_sync(0xffffffffu, v00.y, m);
            v01.x += __shfl_xor_sync(0xffffffffu, v01.x, m);
            v01.y += __shfl_xor_sync(0xffffffffu, v01.y, m);
            v10.x += __shfl_xor_sync(0xffffffffu, v10.x, m);
            v10.y += __shfl_xor_sync(0xffffffffu, v10.y, m);
            v11.x += __shfl_xor_sync(0xffffffffu, v11.x, m);
            v11.y += __shfl_xor_sync(0xffffffffu, v11.y, m);
        }
        // each kh lane finalizes one of the 4 cols, both batches
        {
            int jsel = jq * 4 + kh;                 // local col 0..63
            float s_be = (kh & 2) ? ((kh & 1) ? v10.y : v10.x)
                                  : ((kh & 1) ? v00.y : v00.x);
            float s_bo = (kh & 2) ? ((kh & 1) ? v11.y : v11.x)
                                  : ((kh & 1) ? v01.y : v01.x);
            int beL = bp * 2, boL = beL + 1;
            if (jsel < 32) {                        // r gate -> rhd (local smem)
                int jglob = cg * 32 + jsel;
                size_t re = ((size_t)t * 64 + b0 + beL) * 1024 + jglob;
                float r_be = sigf(s_be + g_Ax[re]);
                float r_bo = sigf(s_bo + g_Ax[re + 1024]);
                int kk2 = jglob >> 1, comp = (jglob & 1) * 2;
                int xh = XS(jglob >> 7);
                float h_be = hdF[(kk2 * 8 + (beL ^ xh)) * 4 + comp];
                float h_bo = hdF[(kk2 * 8 + (boL ^ xh)) * 4 + comp];
                float rh_be = r_be * h_be, rh_bo = r_bo * h_bo;
                rhd[jsel * 8 + beL] = make_float2(rh_be, rh_be);
                rhd[jsel * 8 + boL] = make_float2(rh_bo, rh_bo);
            } else {                                // z gate -> zs (local smem)
                int zl = jsel - 32;
                int axc = 512 + cg * 32 + zl;
                size_t re = ((size_t)t * 64 + b0 + beL) * 1024 + axc;
                zs[zl * 8 + beL] = sigf(s_be + g_Ax[re]);
                zs[zl * 8 + boL] = sigf(s_bo + g_Ax[re + 1024]);
            }
        }
        __syncthreads();

        // ---- phaseB: partial[b][j] += rh_local @ W2h[:, kslice], all 512 j ----
        {
            unsigned long long c[8];
#pragma unroll
            for (int q = 0; q < 8; q++) c[q] = 0ull;
            int j0 = jg * 16;
#pragma unroll 8
            for (int k = 0; k < 32; k++) {
                unsigned long long rv = rhu[k * 8 + bB];
                ulonglong2 w0 = w2u[k * 128 + 0 * 32 + jg];
                ulonglong2 w1 = w2u[k * 128 + 1 * 32 + jg];
                ulonglong2 w2v = w2u[k * 128 + 2 * 32 + jg];
                ulonglong2 w3 = w2u[k * 128 + 3 * 32 + jg];
                fma2(c[0], w0.x, rv); fma2(c[1], w0.y, rv);
                fma2(c[2], w1.x, rv); fma2(c[3], w1.y, rv);
                fma2(c[4], w2v.x, rv); fma2(c[5], w2v.y, rv);
                fma2(c[6], w3.x, rv); fma2(c[7], w3.y, rv);
            }
            float* pb = &g_part[(((size_t)bg * 16 + cg) * 8 + bB) * 512 + j0];
#pragma unroll
            for (int q = 0; q < 8; q++)
                __stcg((float2*)&pb[2 * q], up2(c[q]));
        }
        sense ^= 1; grid_barrier(sense);

        // ---- update: reduce 16 partials, tanh, h = z*h + (1-z)*g ----
        {
            int jglob = cg * 32 + ju;
            float sum = 0.0f;
#pragma unroll
            for (int cgp = 0; cgp < 16; cgp++)
                sum += __ldcg(&g_part[(((size_t)bg * 16 + cgp) * 8 + bu) * 512 + jglob]);
            size_t row = ((size_t)t * 64 + b0 + bu) * 512 + jglob;
            float gg = tanhf(sum + g_Gx[row]);
            float z = zs[ju * 8 + bu];
            int kk2 = jglob >> 1, comp = (jglob & 1) * 2;
            float oldh = hdF[(kk2 * 8 + (bu ^ XS(jglob >> 7))) * 4 + comp];
            float hn = z * oldh + (1.0f - z) * gg;
            __stcg(&g_h[(b0 + bu) * 512 + jglob], hn);
            Y[row] = hn;
            if (t == NT - 1) hs_out[(b0 + bu) * 512 + jglob] = hn;
        }
        sense ^= 1; grid_barrier(sense);
    }
}

extern "C" void kernel_launch(void* const* d_in, const int* in_sizes, int n_in,
                              void* d_out, int out_size) {
    const float* x       = (const float*)d_in[0];  // [512,64,512]
    const float* hiddens = (const float*)d_in[1];  // [2,1,512]
    const float* W1      = (const float*)d_in[2];  // [2,1024,1024]
    const float* b1      = (const float*)d_in[3];  // [2,1024]
    const float* W2      = (const float*)d_in[4];  // [2,512,1024]
    const float* b2      = (const float*)d_in[5];  // [2,512]
    float* out = (float*)d_out;                    // out [T,B,512] then hs [2,B,512]
    float* hs_out = out + (size_t)NT * NB * NH;

    static int attr_done = 0;
    if (!attr_done) {
        cudaFuncSetAttribute(persist_kernel,
                             cudaFuncAttributeMaxDynamicSharedMemorySize, PERSIST_SMEM);
        attr_done = 1;
    }

    for (int layer = 0; layer < 2; layer++) {
        xproj_kernel<<<dim3(12, 256), 256>>>(x, W1, W2, b1, b2, layer, layer == 1);
        persist_kernel<<<NCTA, 256, PERSIST_SMEM>>>(
            hiddens, W1, W2, out, hs_out + (size_t)layer * NB * NH,
            layer, layer == 0);
    }
}